// round 3
// baseline (speedup 1.0000x reference)
#include <cuda_runtime.h>
#include <math.h>

#define NPTS 8192
#define NBATCH 4
#define KNN 30
#define TPB 256
#define CHUNKS (NPTS / TPB)    // 32
#define GRID (NBATCH * CHUNKS) // 128

__global__ __launch_bounds__(TPB) void knn_normals_kernel(
    const float* __restrict__ x, float* __restrict__ out)
{
    extern __shared__ float s[];  // 4 * NPTS floats = 128KB
    float* sx  = s;
    float* sy  = s + NPTS;
    float* sz  = s + 2 * NPTS;
    float* sxx = s + 3 * NPTS;

    const int batch = blockIdx.x / CHUNKS;
    const int chunk = blockIdx.x % CHUNKS;
    const float* __restrict__ xb = x + (size_t)batch * 3 * NPTS;

    // Cooperative load of the whole batch (contiguous 24576 floats) into smem.
    {
        const float4* __restrict__ src = (const float4*)xb;
        float4* dst = (float4*)s;
        #pragma unroll
        for (int t = threadIdx.x; t < 3 * NPTS / 4; t += TPB)
            dst[t] = src[t];
    }
    __syncthreads();

    // xx[j] = (x^2 + y^2) + z^2, each op rounded exactly as the reference
    // (elementwise square, then left-to-right sum over the 3-axis).
    #pragma unroll
    for (int t = threadIdx.x; t < NPTS; t += TPB) {
        float a = __fmul_rn(sx[t], sx[t]);
        float b = __fmul_rn(sy[t], sy[t]);
        float c = __fmul_rn(sz[t], sz[t]);
        sxx[t] = __fadd_rn(__fadd_rn(a, b), c);
    }
    __syncthreads();

    const int i = chunk * TPB + threadIdx.x;
    const float xi = sx[i], yi = sy[i], zi = sz[i];
    const float xxi = sxx[i];

    // Sorted ascending top-30 (distance, index). Strict-< admission + stable
    // placement of equals reproduces top_k lowest-index tie-breaking, and the
    // resulting gather order matches top_k output order.
    float bd[KNN];
    int   bi[KNN];
    #pragma unroll
    for (int t = 0; t < KNN; t++) { bd[t] = 3.4e38f; bi[t] = 0; }
    float thr = 3.4e38f;

    #pragma unroll 4
    for (int j = 0; j < NPTS; j++) {
        // Replicate reference rounding exactly:
        //   dot  = fma(z, z', fma(y, y', x*x'))        (gemm k-loop, fma chain)
        //   pair = (xx_i + xx_j) - 2*dot               (2*dot exact; no fma fuse)
        float dot = __fmaf_rn(zi, sz[j], __fmaf_rn(yi, sy[j], __fmul_rn(xi, sx[j])));
        float d   = __fsub_rn(__fadd_rn(xxi, sxx[j]), __fmul_rn(2.0f, dot));
        if (d < thr) {
            int pos = KNN - 1;
            while (pos > 0 && bd[pos - 1] > d) {
                bd[pos] = bd[pos - 1];
                bi[pos] = bi[pos - 1];
                pos--;
            }
            bd[pos] = d;
            bi[pos] = j;
            thr = bd[KNN - 1];
        }
    }

    // ---- Covariance of the 30 neighbors (double; deviation from the ref's
    // f32 pipeline is ~1e-7 relative, negligible vs eigen-gap) ----
    double s1x = 0, s1y = 0, s1z = 0;
    double sxx2 = 0, sxy = 0, sxz = 0, syy = 0, syz = 0, szz = 0;
    #pragma unroll
    for (int t = 0; t < KNN; t++) {
        int j = bi[t];
        double px = (double)sx[j], py = (double)sy[j], pz = (double)sz[j];
        s1x += px;  s1y += py;  s1z += pz;
        sxx2 += px * px; sxy += px * py; sxz += px * pz;
        syy  += py * py; syz += py * pz; szz += pz * pz;
    }
    const double invK = 1.0 / (double)KNN;
    double cx = s1x * invK, cy = s1y * invK, cz = s1z * invK;
    double a00 = sxx2 - (double)KNN * cx * cx;
    double a01 = sxy  - (double)KNN * cx * cy;
    double a02 = sxz  - (double)KNN * cx * cz;
    double a11 = syy  - (double)KNN * cy * cy;
    double a12 = syz  - (double)KNN * cy * cz;
    double a22 = szz  - (double)KNN * cz * cz;

    // ---- Smallest eigenpair of symmetric 3x3 (closed form, double) ----
    double vx = 1.0, vy = 0.0, vz = 0.0;
    double q  = (a00 + a11 + a22) / 3.0;
    double b00 = a00 - q, b11 = a11 - q, b22 = a22 - q;
    double p2 = b00 * b00 + b11 * b11 + b22 * b22
              + 2.0 * (a01 * a01 + a02 * a02 + a12 * a12);
    if (p2 > 0.0) {
        double p  = sqrt(p2 / 6.0);
        double ip = 1.0 / p;
        double c00 = b00 * ip, c11 = b11 * ip, c22 = b22 * ip;
        double c01 = a01 * ip, c02 = a02 * ip, c12 = a12 * ip;
        double detB = c00 * (c11 * c22 - c12 * c12)
                    - c01 * (c01 * c22 - c12 * c02)
                    + c02 * (c01 * c12 - c11 * c02);
        double r = 0.5 * detB;
        r = fmin(1.0, fmax(-1.0, r));
        double phi = acos(r) / 3.0;
        double lam = q + 2.0 * p * cos(phi + 2.0943951023931953); // smallest

        double m00 = a00 - lam, m11 = a11 - lam, m22 = a22 - lam;
        double u0x = a01 * a12 - a02 * m11;
        double u0y = a02 * a01 - m00 * a12;
        double u0z = m00 * m11 - a01 * a01;   // r0 x r1
        double u1x = a01 * m22 - a02 * a12;
        double u1y = a02 * a02 - m00 * m22;
        double u1z = m00 * a12 - a01 * a02;   // r0 x r2
        double u2x = m11 * m22 - a12 * a12;
        double u2y = a12 * a02 - a01 * m22;
        double u2z = a01 * a12 - m11 * a02;   // r1 x r2
        double n0 = u0x * u0x + u0y * u0y + u0z * u0z;
        double n1 = u1x * u1x + u1y * u1y + u1z * u1z;
        double n2 = u2x * u2x + u2y * u2y + u2z * u2z;
        double bx = u0x, by = u0y, bz = u0z, bn = n0;
        if (n1 > bn) { bx = u1x; by = u1y; bz = u1z; bn = n1; }
        if (n2 > bn) { bx = u2x; by = u2y; bz = u2z; bn = n2; }
        if (bn > 0.0) {
            double inv = rsqrt(bn);
            vx = bx * inv; vy = by * inv; vz = bz * inv;
        }
    }

    // ---- Orientation: flip so that dot(-x, v) >= 0 ----
    double dot = -((double)xi * vx + (double)yi * vy + (double)zi * vz);
    if (dot < 0.0) { vx = -vx; vy = -vy; vz = -vz; }

    // ---- Output: (4, 6, 8192): rows 0-2 copy of x, rows 3-5 normals ----
    float* __restrict__ ob = out + (size_t)batch * 6 * NPTS;
    ob[0 * NPTS + i] = xi;
    ob[1 * NPTS + i] = yi;
    ob[2 * NPTS + i] = zi;
    ob[3 * NPTS + i] = (float)vx;
    ob[4 * NPTS + i] = (float)vy;
    ob[5 * NPTS + i] = (float)vz;
}

extern "C" void kernel_launch(void* const* d_in, const int* in_sizes, int n_in,
                              void* d_out, int out_size)
{
    (void)in_sizes; (void)n_in; (void)out_size;
    const float* x = (const float*)d_in[0];
    float* out = (float*)d_out;

    const int smem = 4 * NPTS * sizeof(float);  // 131072 bytes
    cudaFuncSetAttribute(knn_normals_kernel,
                         cudaFuncAttributeMaxDynamicSharedMemorySize, smem);
    knn_normals_kernel<<<GRID, TPB, smem>>>(x, out);
}

// round 6
// speedup vs baseline: 2.9409x; 2.9409x over previous
#include <cuda_runtime.h>
#include <math.h>

#define NPTS 8192
#define NBATCH 4
#define KNN 30
#define TPB 256
#define CHUNKS (NPTS / TPB)    // 32
#define GRID (NBATCH * CHUNKS) // 128

// Sentinel = key of (+FLT_MAX, index 0x1FFF). Decodes to thr = FLT_MAX (finite),
// larger than every real key. ord(FLT_MAX) = 0x7F7FFFFF ^ 0x80000000 = 0xFF7FFFFF.
#define SENTINEL ((0xFF7FFFFFull << 13) | 0x1FFFull)

__global__ __launch_bounds__(TPB) void knn_normals_kernel(
    const float* __restrict__ x, float* __restrict__ out)
{
    extern __shared__ float4 s4[];  // NPTS float4 = 128KB: (x, y, z, xx)
    const int batch = blockIdx.x / CHUNKS;
    const int chunk = blockIdx.x % CHUNKS;
    const float* __restrict__ xb = x + (size_t)batch * 3 * NPTS;

    // Build (x, y, z, xx) in smem. xx rounded exactly as the reference:
    // elementwise squares, then left-to-right sum over the 3 components.
    for (int t = threadIdx.x; t < NPTS; t += TPB) {
        float a = xb[t];
        float b = xb[NPTS + t];
        float c = xb[2 * NPTS + t];
        float xx = __fadd_rn(__fadd_rn(__fmul_rn(a, a), __fmul_rn(b, b)),
                             __fmul_rn(c, c));
        s4[t] = make_float4(a, b, c, xx);
    }
    __syncthreads();

    const int i = chunk * TPB + threadIdx.x;
    const float4 pi = s4[i];
    const float xi = pi.x, yi = pi.y, zi = pi.z, xxi = pi.w;

    // Top-30 smallest (dist, index) as u64 keys, register-resident,
    // sorted DESCENDING (bk[0] = worst). Key = (ordered_uint(d) << 13) | j.
    unsigned long long bk[KNN];
    #pragma unroll
    for (int t = 0; t < KNN; t++) bk[t] = SENTINEL;
    float thr = 3.4028235e38f;  // FLT_MAX, matches decoded sentinel

    #pragma unroll 4
    for (int j = 0; j < NPTS; j++) {
        float4 pj = s4[j];
        // Exact reference rounding:
        //   dot  = fma(z,z', fma(y,y', x*x'))
        //   d    = (xx_i + xx_j) - 2*dot     (no fma contraction)
        float dot = __fmaf_rn(zi, pj.z, __fmaf_rn(yi, pj.y, __fmul_rn(xi, pj.x)));
        float d   = __fsub_rn(__fadd_rn(xxi, pj.w), __fmul_rn(2.0f, dot));
        // Strict < is exact: current j exceeds every index in the list, so
        // d == thr must reject (top_k keeps the lower index).
        if (d < thr) {
            unsigned ub = __float_as_uint(d);
            ub ^= ((unsigned)(((int)ub) >> 31)) | 0x80000000u;  // order-preserving
            unsigned long long Kn = ((unsigned long long)ub << 13) | (unsigned)j;
            // Branch-free unrolled shift-insert: evict bk[0], place Kn.
            bool prev = true;
            #pragma unroll
            for (int t = 0; t < KNN; t++) {
                bool cur = (t < KNN - 1) ? (bk[t + 1] > Kn) : false;
                unsigned long long below = (t < KNN - 1) ? bk[t + 1] : 0ull;
                unsigned long long keep = bk[t];
                bk[t] = cur ? below : (prev ? Kn : keep);
                prev = cur;
            }
            // New float threshold from the new worst key.
            unsigned ut = (unsigned)(bk[0] >> 13);
            ut = (ut & 0x80000000u) ? (ut & 0x7FFFFFFFu) : ~ut;
            thr = __uint_as_float(ut);
        }
    }

    // ---- Covariance of the 30 neighbors (double; order-invariant) ----
    double s1x = 0, s1y = 0, s1z = 0;
    double sxx2 = 0, sxy = 0, sxz = 0, syy = 0, syz = 0, szz = 0;
    #pragma unroll
    for (int t = 0; t < KNN; t++) {
        int j = (int)(bk[t] & 0x1FFFull);
        float4 p = s4[j];
        double px = (double)p.x, py = (double)p.y, pz = (double)p.z;
        s1x += px;  s1y += py;  s1z += pz;
        sxx2 += px * px; sxy += px * py; sxz += px * pz;
        syy  += py * py; syz += py * pz; szz += pz * pz;
    }
    const double invK = 1.0 / (double)KNN;
    double cx = s1x * invK, cy = s1y * invK, cz = s1z * invK;
    double a00 = sxx2 - (double)KNN * cx * cx;
    double a01 = sxy  - (double)KNN * cx * cy;
    double a02 = sxz  - (double)KNN * cx * cz;
    double a11 = syy  - (double)KNN * cy * cy;
    double a12 = syz  - (double)KNN * cy * cz;
    double a22 = szz  - (double)KNN * cz * cz;

    // ---- Smallest eigenpair of symmetric 3x3 (closed form, double) ----
    double vx = 1.0, vy = 0.0, vz = 0.0;
    double q  = (a00 + a11 + a22) / 3.0;
    double b00 = a00 - q, b11 = a11 - q, b22 = a22 - q;
    double p2 = b00 * b00 + b11 * b11 + b22 * b22
              + 2.0 * (a01 * a01 + a02 * a02 + a12 * a12);
    if (p2 > 0.0) {
        double p  = sqrt(p2 / 6.0);
        double ip = 1.0 / p;
        double c00 = b00 * ip, c11 = b11 * ip, c22 = b22 * ip;
        double c01 = a01 * ip, c02 = a02 * ip, c12 = a12 * ip;
        double detB = c00 * (c11 * c22 - c12 * c12)
                    - c01 * (c01 * c22 - c12 * c02)
                    + c02 * (c01 * c12 - c11 * c02);
        double r = 0.5 * detB;
        r = fmin(1.0, fmax(-1.0, r));
        double phi = acos(r) / 3.0;
        double lam = q + 2.0 * p * cos(phi + 2.0943951023931953); // smallest

        double m00 = a00 - lam, m11 = a11 - lam, m22 = a22 - lam;
        double u0x = a01 * a12 - a02 * m11;
        double u0y = a02 * a01 - m00 * a12;
        double u0z = m00 * m11 - a01 * a01;   // r0 x r1
        double u1x = a01 * m22 - a02 * a12;
        double u1y = a02 * a02 - m00 * m22;
        double u1z = m00 * a12 - a01 * a02;   // r0 x r2
        double u2x = m11 * m22 - a12 * a12;
        double u2y = a12 * a02 - a01 * m22;
        double u2z = a01 * a12 - m11 * a02;   // r1 x r2
        double n0 = u0x * u0x + u0y * u0y + u0z * u0z;
        double n1 = u1x * u1x + u1y * u1y + u1z * u1z;
        double n2 = u2x * u2x + u2y * u2y + u2z * u2z;
        double bx = u0x, by = u0y, bz = u0z, bn = n0;
        if (n1 > bn) { bx = u1x; by = u1y; bz = u1z; bn = n1; }
        if (n2 > bn) { bx = u2x; by = u2y; bz = u2z; bn = n2; }
        if (bn > 0.0) {
            double inv = rsqrt(bn);
            vx = bx * inv; vy = by * inv; vz = bz * inv;
        }
    }

    // ---- Orientation: flip so that dot(-x, v) >= 0 ----
    double dot = -((double)xi * vx + (double)yi * vy + (double)zi * vz);
    if (dot < 0.0) { vx = -vx; vy = -vy; vz = -vz; }

    // ---- Output: (4, 6, 8192): rows 0-2 copy of x, rows 3-5 normals ----
    float* __restrict__ ob = out + (size_t)batch * 6 * NPTS;
    ob[0 * NPTS + i] = xi;
    ob[1 * NPTS + i] = yi;
    ob[2 * NPTS + i] = zi;
    ob[3 * NPTS + i] = (float)vx;
    ob[4 * NPTS + i] = (float)vy;
    ob[5 * NPTS + i] = (float)vz;
}

extern "C" void kernel_launch(void* const* d_in, const int* in_sizes, int n_in,
                              void* d_out, int out_size)
{
    (void)in_sizes; (void)n_in; (void)out_size;
    const float* x = (const float*)d_in[0];
    float* out = (float*)d_out;

    const int smem = NPTS * sizeof(float4);  // 131072 bytes
    cudaFuncSetAttribute(knn_normals_kernel,
                         cudaFuncAttributeMaxDynamicSharedMemorySize, smem);
    knn_normals_kernel<<<GRID, TPB, smem>>>(x, out);
}

// round 8
// speedup vs baseline: 4.8010x; 1.6325x over previous
#include <cuda_runtime.h>
#include <math.h>

#define NPTS 8192
#define NBATCH 4
#define KNN 30
#define TPB 256
#define CHUNKS (NPTS / TPB)    // 32
#define GRID (NBATCH * CHUNKS) // 128

// smem layout (bytes): float4 s4[NPTS] | int strict[KNN][TPB] | int ties[KNN][TPB]
#define SMEM_BYTES (NPTS * 16 + KNN * TPB * 4 + KNN * TPB * 4)

__global__ __launch_bounds__(TPB) void knn_normals_kernel(
    const float* __restrict__ x, float* __restrict__ out)
{
    extern __shared__ char smem_raw[];
    float4* s4     = (float4*)smem_raw;                       // 128KB
    int*    sstrict = (int*)(smem_raw + NPTS * 16);           // 30KB
    int*    sties   = (int*)(smem_raw + NPTS * 16 + KNN * TPB * 4); // 30KB

    const int batch = blockIdx.x / CHUNKS;
    const int chunk = blockIdx.x % CHUNKS;
    const float* __restrict__ xb = x + (size_t)batch * 3 * NPTS;

    // Build (x, y, z, xx) in smem. xx rounded exactly as the reference:
    // elementwise squares, then left-to-right sum over the 3 components.
    for (int t = threadIdx.x; t < NPTS; t += TPB) {
        float a = xb[t];
        float b = xb[NPTS + t];
        float c = xb[2 * NPTS + t];
        float xx = __fadd_rn(__fadd_rn(__fmul_rn(a, a), __fmul_rn(b, b)),
                             __fmul_rn(c, c));
        s4[t] = make_float4(a, b, c, xx);
    }
    __syncthreads();

    const int i = chunk * TPB + threadIdx.x;
    const float4 pi = s4[i];
    const float xi = pi.x, yi = pi.y, zi = pi.z, xxi = pi.w;

    // ---- Pass 1: 30 smallest distance VALUES, sorted descending (bd[0]=max).
    // Replace-max + single FMNMX bubble pass per admission.
    float bd[KNN];
    #pragma unroll
    for (int t = 0; t < KNN; t++) bd[t] = 3.4028235e38f;
    float thr = 3.4028235e38f;

    #pragma unroll 4
    for (int j = 0; j < NPTS; j++) {
        float4 pj = s4[j];
        // Exact reference rounding:
        //   dot = fma(z,z', fma(y,y', x*x'));  d = (xx_i + xx_j) - 2*dot
        float dot = __fmaf_rn(zi, pj.z, __fmaf_rn(yi, pj.y, __fmul_rn(xi, pj.x)));
        float d   = __fsub_rn(__fadd_rn(xxi, pj.w), __fmul_rn(2.0f, dot));
        if (d < thr) {
            bd[0] = d;
            #pragma unroll
            for (int t = 0; t < KNN - 1; t++) {
                float a = bd[t], b = bd[t + 1];
                bd[t]     = fmaxf(a, b);
                bd[t + 1] = fminf(a, b);
            }
            thr = bd[0];
        }
    }
    // thr == 30th smallest distance value (multiset order statistic).

    // ---- Pass 2: recompute distances, collect indices.
    // strict (d < thr): at most 29 by definition of the order statistic.
    // ties (d == thr): ascending j; first (KNN - m) of them complete the set,
    // exactly matching top_k lowest-index tie-breaking.
    int cnt_s = 0, cnt_t = 0;
    #pragma unroll 4
    for (int j = 0; j < NPTS; j++) {
        float4 pj = s4[j];
        float dot = __fmaf_rn(zi, pj.z, __fmaf_rn(yi, pj.y, __fmul_rn(xi, pj.x)));
        float d   = __fsub_rn(__fadd_rn(xxi, pj.w), __fmul_rn(2.0f, dot));
        if (d <= thr) {
            if (d < thr) {
                sstrict[cnt_s * TPB + threadIdx.x] = j;
                cnt_s++;
            } else if (cnt_t < KNN) {
                sties[cnt_t * TPB + threadIdx.x] = j;
                cnt_t++;
            }
        }
    }

    // ---- Covariance of the 30 neighbors (double; order-invariant) ----
    double s1x = 0, s1y = 0, s1z = 0;
    double sxx2 = 0, sxy = 0, sxz = 0, syy = 0, syz = 0, szz = 0;
    #pragma unroll
    for (int t = 0; t < KNN; t++) {
        int j = (t < cnt_s) ? sstrict[t * TPB + threadIdx.x]
                            : sties[(t - cnt_s) * TPB + threadIdx.x];
        float4 p = s4[j];
        double px = (double)p.x, py = (double)p.y, pz = (double)p.z;
        s1x += px;  s1y += py;  s1z += pz;
        sxx2 += px * px; sxy += px * py; sxz += px * pz;
        syy  += py * py; syz += py * pz; szz += pz * pz;
    }
    const double invK = 1.0 / (double)KNN;
    double cx = s1x * invK, cy = s1y * invK, cz = s1z * invK;
    double a00 = sxx2 - (double)KNN * cx * cx;
    double a01 = sxy  - (double)KNN * cx * cy;
    double a02 = sxz  - (double)KNN * cx * cz;
    double a11 = syy  - (double)KNN * cy * cy;
    double a12 = syz  - (double)KNN * cy * cz;
    double a22 = szz  - (double)KNN * cz * cz;

    // ---- Smallest eigenpair of symmetric 3x3 (closed form, double) ----
    double vx = 1.0, vy = 0.0, vz = 0.0;
    double q  = (a00 + a11 + a22) / 3.0;
    double b00 = a00 - q, b11 = a11 - q, b22 = a22 - q;
    double p2 = b00 * b00 + b11 * b11 + b22 * b22
              + 2.0 * (a01 * a01 + a02 * a02 + a12 * a12);
    if (p2 > 0.0) {
        double p  = sqrt(p2 / 6.0);
        double ip = 1.0 / p;
        double c00 = b00 * ip, c11 = b11 * ip, c22 = b22 * ip;
        double c01 = a01 * ip, c02 = a02 * ip, c12 = a12 * ip;
        double detB = c00 * (c11 * c22 - c12 * c12)
                    - c01 * (c01 * c22 - c12 * c02)
                    + c02 * (c01 * c12 - c11 * c02);
        double r = 0.5 * detB;
        r = fmin(1.0, fmax(-1.0, r));
        double phi = acos(r) / 3.0;
        double lam = q + 2.0 * p * cos(phi + 2.0943951023931953); // smallest

        double m00 = a00 - lam, m11 = a11 - lam, m22 = a22 - lam;
        double u0x = a01 * a12 - a02 * m11;
        double u0y = a02 * a01 - m00 * a12;
        double u0z = m00 * m11 - a01 * a01;   // r0 x r1
        double u1x = a01 * m22 - a02 * a12;
        double u1y = a02 * a02 - m00 * m22;
        double u1z = m00 * a12 - a01 * a02;   // r0 x r2
        double u2x = m11 * m22 - a12 * a12;
        double u2y = a12 * a02 - a01 * m22;
        double u2z = a01 * a12 - m11 * a02;   // r1 x r2
        double n0 = u0x * u0x + u0y * u0y + u0z * u0z;
        double n1 = u1x * u1x + u1y * u1y + u1z * u1z;
        double n2 = u2x * u2x + u2y * u2y + u2z * u2z;
        double bx = u0x, by = u0y, bz = u0z, bn = n0;
        if (n1 > bn) { bx = u1x; by = u1y; bz = u1z; bn = n1; }
        if (n2 > bn) { bx = u2x; by = u2y; bz = u2z; bn = n2; }
        if (bn > 0.0) {
            double inv = rsqrt(bn);
            vx = bx * inv; vy = by * inv; vz = bz * inv;
        }
    }

    // ---- Orientation: flip so that dot(-x, v) >= 0 ----
    double dot = -((double)xi * vx + (double)yi * vy + (double)zi * vz);
    if (dot < 0.0) { vx = -vx; vy = -vy; vz = -vz; }

    // ---- Output: (4, 6, 8192): rows 0-2 copy of x, rows 3-5 normals ----
    float* __restrict__ ob = out + (size_t)batch * 6 * NPTS;
    ob[0 * NPTS + i] = xi;
    ob[1 * NPTS + i] = yi;
    ob[2 * NPTS + i] = zi;
    ob[3 * NPTS + i] = (float)vx;
    ob[4 * NPTS + i] = (float)vy;
    ob[5 * NPTS + i] = (float)vz;
}

extern "C" void kernel_launch(void* const* d_in, const int* in_sizes, int n_in,
                              void* d_out, int out_size)
{
    (void)in_sizes; (void)n_in; (void)out_size;
    const float* x = (const float*)d_in[0];
    float* out = (float*)d_out;

    const int smem = SMEM_BYTES;  // 131072 + 30720 + 30720 = 192512 bytes
    cudaFuncSetAttribute(knn_normals_kernel,
                         cudaFuncAttributeMaxDynamicSharedMemorySize, smem);
    knn_normals_kernel<<<GRID, TPB, smem>>>(x, out);
}